// round 2
// baseline (speedup 1.0000x reference)
#include <cuda_runtime.h>
#include <cuda_bf16.h>
#include <math.h>

// Problem constants
#define BATCH 4
#define TLEN 1024
#define EMB 512
#define VOC 50257
#define MALL (BATCH * TLEN)          // 4096 rows
static __device__ float g_X[MALL * EMB];
static __device__ float g_K[MALL * EMB];
static __device__ float g_Q[MALL * EMB];
static __device__ float g_V[MALL * EMB];
static __device__ float g_WEI[BATCH * TLEN * TLEN];   // wei -> att in place
static __device__ float g_O[MALL * EMB];
static __device__ float g_cmax[BATCH * TLEN];
static __device__ float g_csum[BATCH * TLEN];
static __device__ float g_rowloss[MALL];

// ---------------------------------------------------------------------------
// Embedding: x[n,:] = tok_emb[idx[n],:] + pos_emb[n % T,:]
// ---------------------------------------------------------------------------
__global__ void embed_kernel(const int* __restrict__ idx,
                             const float* __restrict__ tok,
                             const float* __restrict__ pos,
                             float* __restrict__ x) {
    int n = blockIdx.x;                 // 0..4095
    int t = n & (TLEN - 1);
    int e4 = threadIdx.x;               // 0..127 (float4 index)
    int token = __ldg(&idx[n]);
    float4 a = *(const float4*)&tok[(size_t)token * EMB + e4 * 4];
    float4 p = *(const float4*)&pos[(size_t)t * EMB + e4 * 4];
    a.x += p.x; a.y += p.y; a.z += p.z; a.w += p.w;
    *(float4*)&x[(size_t)n * EMB + e4 * 4] = a;
}

// ---------------------------------------------------------------------------
// Tiled SIMT GEMM. C = alpha * A * op(B) + bias
//   NT=false: B is row-major [K,N]   (C[m,n] = sum_k A[m,k]*B[k,n])
//   NT=true : B is row-major [N,K]   (C[m,n] = sum_k A[m,k]*B[n,k])
//   VEC=false: scalar B loads / C stores (for ldb/ldc not divisible by 4,
//              e.g. VOC=50257 — float4 there traps with misaligned address).
// Requirements: M % 128 == 0, K % 8 == 0, lda % 4 == 0. N may be ragged.
// Batched via blockIdx.z with element strides sA/sB/sC.
// ---------------------------------------------------------------------------
template <bool NT, bool VEC>
__global__ __launch_bounds__(256)
void gemm_kernel(const float* __restrict__ A, const float* __restrict__ B,
                 float* __restrict__ C,
                 int M, int N, int K, int lda, int ldb, int ldc,
                 long long sA, long long sB, long long sC,
                 float alpha, const float* __restrict__ bias) {
    constexpr int BM = 128, BN = 128, BK = 8, TM = 8, TN = 8;
    __shared__ float As[BK][BM];
    __shared__ float Bs[BK][BN];

    A += (long long)blockIdx.z * sA;
    B += (long long)blockIdx.z * sB;
    C += (long long)blockIdx.z * sC;

    const int tid = threadIdx.x;
    const int tx = tid % 16;
    const int ty = tid / 16;
    const int m0 = blockIdx.y * BM;
    const int n0 = blockIdx.x * BN;

    float acc[TM][TN];
#pragma unroll
    for (int i = 0; i < TM; ++i)
#pragma unroll
        for (int j = 0; j < TN; ++j) acc[i][j] = 0.f;

    // A tile loader mapping: 2 threads per row, float4 each (lda % 4 == 0)
    const int arow = tid >> 1;          // 0..127
    const int acol = (tid & 1) * 4;     // 0 or 4

    for (int k0 = 0; k0 < K; k0 += BK) {
        // ---- load A tile (transpose into As[k][m]) ----
        {
            float4 av = *(const float4*)&A[(size_t)(m0 + arow) * lda + (k0 + acol)];
            As[acol + 0][arow] = av.x;
            As[acol + 1][arow] = av.y;
            As[acol + 2][arow] = av.z;
            As[acol + 3][arow] = av.w;
        }
        // ---- load B tile ----
        if (!NT) {
            int brow = tid >> 5;             // 0..7  (k)
            int bcol = (tid & 31) * 4;       // 0..124 (n)
            int gn = n0 + bcol;
            const float* bp = &B[(size_t)(k0 + brow) * ldb + gn];
            float4 bv;
            if (VEC && gn + 3 < N) {
                bv = *(const float4*)bp;
            } else {
                bv.x = (gn + 0 < N) ? bp[0] : 0.f;
                bv.y = (gn + 1 < N) ? bp[1] : 0.f;
                bv.z = (gn + 2 < N) ? bp[2] : 0.f;
                bv.w = (gn + 3 < N) ? bp[3] : 0.f;
            }
            *(float4*)&Bs[brow][bcol] = bv;
        } else {
            int brow = tid >> 1;             // 0..127 (n)
            int bcol = (tid & 1) * 4;        // 0 or 4 (k)
            int gn = n0 + brow;
            float4 bv = make_float4(0.f, 0.f, 0.f, 0.f);
            if (gn < N) {
                const float* bp = &B[(size_t)gn * ldb + (k0 + bcol)];
                if (VEC) bv = *(const float4*)bp;
                else { bv.x = bp[0]; bv.y = bp[1]; bv.z = bp[2]; bv.w = bp[3]; }
            }
            Bs[bcol + 0][brow] = bv.x;
            Bs[bcol + 1][brow] = bv.y;
            Bs[bcol + 2][brow] = bv.z;
            Bs[bcol + 3][brow] = bv.w;
        }
        __syncthreads();

#pragma unroll
        for (int k = 0; k < BK; ++k) {
            float af[TM], bf[TN];
#pragma unroll
            for (int i = 0; i < TM; ++i) af[i] = As[k][ty * TM + i];
#pragma unroll
            for (int j = 0; j < TN; ++j) bf[j] = Bs[k][tx * TN + j];
#pragma unroll
            for (int i = 0; i < TM; ++i)
#pragma unroll
                for (int j = 0; j < TN; ++j)
                    acc[i][j] = fmaf(af[i], bf[j], acc[i][j]);
        }
        __syncthreads();
    }

    // ---- epilogue ----
#pragma unroll
    for (int i = 0; i < TM; ++i) {
        int m = m0 + ty * TM + i;
        float* crow = C + (size_t)m * ldc;
#pragma unroll
        for (int j0 = 0; j0 < TN; j0 += 4) {
            int n = n0 + tx * TN + j0;
            if (VEC && n + 3 < N) {
                float4 r;
                r.x = alpha * acc[i][j0 + 0];
                r.y = alpha * acc[i][j0 + 1];
                r.z = alpha * acc[i][j0 + 2];
                r.w = alpha * acc[i][j0 + 3];
                if (bias) {
                    r.x += bias[n + 0]; r.y += bias[n + 1];
                    r.z += bias[n + 2]; r.w += bias[n + 3];
                }
                *(float4*)&crow[n] = r;
            } else {
#pragma unroll
                for (int q = 0; q < 4; ++q) {
                    int nn = n + q;
                    if (nn < N)
                        crow[nn] = alpha * acc[i][j0 + q] + (bias ? bias[nn] : 0.f);
                }
            }
        }
    }
}

// ---------------------------------------------------------------------------
// Column softmax stats: for each (b, s) compute max / sumexp over t >= s
// (softmax over the QUERY axis, faithful to the reference's axis=1).
// ---------------------------------------------------------------------------
__global__ void colstats_kernel(const float* __restrict__ wei,
                                float* __restrict__ cmax,
                                float* __restrict__ csum) {
    int b = blockIdx.y;
    int s = blockIdx.x * 32 + threadIdx.x;
    int ty = threadIdx.y;  // 0..7
    const float* w = wei + (size_t)b * TLEN * TLEN;
    float m = -INFINITY, l = 0.f;
    for (int t = ty; t < TLEN; t += 8) {
        if (t >= s) {
            float x = w[(size_t)t * TLEN + s];
            float nm = fmaxf(m, x);
            l = l * __expf(m - nm) + __expf(x - nm);
            m = nm;
        }
    }
    __shared__ float sm[8][33];
    __shared__ float sl[8][33];
    sm[ty][threadIdx.x] = m;
    sl[ty][threadIdx.x] = l;
    __syncthreads();
    if (ty == 0) {
        for (int j = 1; j < 8; ++j) {
            float m2 = sm[j][threadIdx.x], l2 = sl[j][threadIdx.x];
            if (l2 > 0.f) {
                float nm = fmaxf(m, m2);
                l = l * __expf(m - nm) + l2 * __expf(m2 - nm);
                m = nm;
            }
        }
        cmax[b * TLEN + s] = m;
        csum[b * TLEN + s] = l;
    }
}

// att[b,t,s] = (t>=s) ? exp(wei - cmax[b,s]) / csum[b,s] : 0   (in place)
__global__ void att_kernel(float* __restrict__ wei,
                           const float* __restrict__ cmax,
                           const float* __restrict__ csum) {
    int i = blockIdx.x * blockDim.x + threadIdx.x;   // exact cover: 4*2^20
    int b = i >> 20;
    int r = i & (TLEN * TLEN - 1);
    int t = r >> 10;
    int s = r & (TLEN - 1);
    float v = 0.f;
    if (t >= s)
        v = __expf(wei[i] - cmax[b * TLEN + s]) / csum[b * TLEN + s];
    wei[i] = v;
}

// ---------------------------------------------------------------------------
// Per-row NLL: rowloss[r] = logsumexp(logits[r,:]) - logits[r, target[r]]
// ---------------------------------------------------------------------------
__global__ void rowloss_kernel(const float* __restrict__ logits,
                               const int* __restrict__ target,
                               float* __restrict__ rowloss) {
    int row = blockIdx.x;
    const float* p = logits + (size_t)row * VOC;
    float m = -INFINITY, l = 0.f;
    for (int j = threadIdx.x; j < VOC; j += blockDim.x) {
        float x = p[j];
        float nm = fmaxf(m, x);
        l = l * expf(m - nm) + expf(x - nm);
        m = nm;
    }
#pragma unroll
    for (int off = 16; off; off >>= 1) {
        float m2 = __shfl_xor_sync(0xFFFFFFFFu, m, off);
        float l2 = __shfl_xor_sync(0xFFFFFFFFu, l, off);
        float nm = fmaxf(m, m2);
        l = l * expf(m - nm) + l2 * expf(m2 - nm);
        m = nm;
    }
    __shared__ float sm[8], sl[8];
    int w = threadIdx.x >> 5;
    if ((threadIdx.x & 31) == 0) { sm[w] = m; sl[w] = l; }
    __syncthreads();
    if (threadIdx.x == 0) {
        m = sm[0]; l = sl[0];
        for (int j = 1; j < 8; ++j) {
            float m2 = sm[j], l2 = sl[j];
            float nm = fmaxf(m, m2);
            l = l * expf(m - nm) + l2 * expf(m2 - nm);
            m = nm;
        }
        float lse = m + logf(l);
        rowloss[row] = lse - p[target[row]];
    }
}

__global__ void loss_reduce_kernel(const float* __restrict__ rowloss,
                                   float* __restrict__ out) {
    __shared__ float s[256];
    float acc = 0.f;
    for (int j = threadIdx.x; j < MALL; j += 256) acc += rowloss[j];
    s[threadIdx.x] = acc;
    __syncthreads();
    for (int o = 128; o; o >>= 1) {
        if (threadIdx.x < o) s[threadIdx.x] += s[threadIdx.x + o];
        __syncthreads();
    }
    if (threadIdx.x == 0) *out = s[0] / (float)MALL;
}

// ---------------------------------------------------------------------------
extern "C" void kernel_launch(void* const* d_in, const int* in_sizes, int n_in,
                              void* d_out, int out_size) {
    const int*   idx    = (const int*)d_in[0];
    const int*   target = (const int*)d_in[1];
    const float* tok    = (const float*)d_in[2];
    const float* pos    = (const float*)d_in[3];
    const float* Wk     = (const float*)d_in[4];
    const float* Wq     = (const float*)d_in[5];
    const float* Wv     = (const float*)d_in[6];
    const float* Wlm    = (const float*)d_in[7];
    const float* blm    = (const float*)d_in[8];
    float* out = (float*)d_out;

    float *X, *Kb, *Qb, *Vb, *WEI, *O, *cmax, *csum, *rl;
    cudaGetSymbolAddress((void**)&X,    g_X);
    cudaGetSymbolAddress((void**)&Kb,   g_K);
    cudaGetSymbolAddress((void**)&Qb,   g_Q);
    cudaGetSymbolAddress((void**)&Vb,   g_V);
    cudaGetSymbolAddress((void**)&WEI,  g_WEI);
    cudaGetSymbolAddress((void**)&O,    g_O);
    cudaGetSymbolAddress((void**)&cmax, g_cmax);
    cudaGetSymbolAddress((void**)&csum, g_csum);
    cudaGetSymbolAddress((void**)&rl,   g_rowloss);

    const float scale = 0.044194173824159216f;  // 512^-0.5 (n_embed, not head)

    // 1) x = tok_emb[idx] + pos_emb
    embed_kernel<<<MALL, 128>>>(idx, tok, pos, X);

    // 2) k,q,v = x @ W  ([4096,512] x [512,512])
    {
        dim3 g(EMB / 128, MALL / 128, 1);
        gemm_kernel<false, true><<<g, 256>>>(X, Wk, Kb, MALL, EMB, EMB, EMB, EMB, EMB,
                                             0, 0, 0, 1.f, nullptr);
        gemm_kernel<false, true><<<g, 256>>>(X, Wq, Qb, MALL, EMB, EMB, EMB, EMB, EMB,
                                             0, 0, 0, 1.f, nullptr);
        gemm_kernel<false, true><<<g, 256>>>(X, Wv, Vb, MALL, EMB, EMB, EMB, EMB, EMB,
                                             0, 0, 0, 1.f, nullptr);
    }

    // 3) wei = scale * q @ k^T  (batched NT, per-batch [1024,512]x[1024,512]^T)
    {
        dim3 g(TLEN / 128, TLEN / 128, BATCH);
        gemm_kernel<true, true><<<g, 256>>>(Qb, Kb, WEI, TLEN, TLEN, EMB, EMB, EMB, TLEN,
                                            (long long)TLEN * EMB, (long long)TLEN * EMB,
                                            (long long)TLEN * TLEN, scale, nullptr);
    }

    // 4) softmax over the query axis (per key column, causal-masked)
    colstats_kernel<<<dim3(TLEN / 32, BATCH), dim3(32, 8)>>>(WEI, cmax, csum);
    att_kernel<<<(BATCH * TLEN * TLEN) / 256, 256>>>(WEI, cmax, csum);

    // 5) out = att @ v  (batched NN [1024,1024]x[1024,512])
    {
        dim3 g(EMB / 128, TLEN / 128, BATCH);
        gemm_kernel<false, true><<<g, 256>>>(WEI, Vb, O, TLEN, EMB, TLEN, TLEN, EMB, EMB,
                                             (long long)TLEN * TLEN, (long long)TLEN * EMB,
                                             (long long)TLEN * EMB, 1.f, nullptr);
    }

    // 6) logits = out @ W_lm + b_lm  ([4096,512]x[512,50257]) -> d_out
    //    VOC = 50257 is odd: no 16B-aligned float4 access possible -> VEC=false
    {
        dim3 g((VOC + 127) / 128, MALL / 128, 1);
        gemm_kernel<false, false><<<g, 256>>>(O, Wlm, out, MALL, VOC, EMB, EMB, VOC, VOC,
                                              0, 0, 0, 1.f, blm);
    }

    // 7) loss = mean(logsumexp(row) - logit[target])
    rowloss_kernel<<<MALL, 256>>>(out, target, rl);
    loss_reduce_kernel<<<1, 256>>>(rl, out + (size_t)out_size - 1);
}

// round 4
// speedup vs baseline: 2.3370x; 2.3370x over previous
#include <cuda_runtime.h>
#include <cuda_bf16.h>
#include <math.h>
#include <stdint.h>

// Problem constants
#define BATCH 4
#define TLEN 1024
#define EMB 512
#define VOC 50257
#define MALL (BATCH * TLEN)          // 4096 rows

// lm_head mma.sync tiling
#define BM 128
#define BN 128
#define BKC 32                        // k per chunk (bf16)
#define NCHUNK (EMB / BKC)            // 16
#define NTILES_M (MALL / BM)          // 32
#define NTILES_N 393                  // ceil(50257/128)
#define N_PAD (NTILES_N * BN)         // 50304
#define ROWB 80                       // SMEM row stride bytes (conflict-free)
#define TILE_SM (128 * ROWB)          // 10240 B per tile
#define STAGE_SM (4 * TILE_SM)        // AH, AL, BH, BL
#define SMEM_TOTAL_TC (2 * STAGE_SM)  // 81920

static __device__ float g_X[MALL * EMB];
static __device__ float g_K[MALL * EMB];
static __device__ float g_Q[MALL * EMB];
static __device__ float g_V[MALL * EMB];
static __device__ float g_WEI[BATCH * TLEN * TLEN];   // wei -> att in place
static __device__ float g_O[MALL * EMB];
static __device__ float g_cmax[BATCH * TLEN];
static __device__ float g_csum[BATCH * TLEN];
static __device__ float g_rowloss[MALL];
// split-bf16 operands for lm_head MMA GEMM
static __device__ __nv_bfloat16 g_Ah[MALL * EMB];
static __device__ __nv_bfloat16 g_Al[MALL * EMB];
static __device__ __nv_bfloat16 g_Bth[(size_t)N_PAD * EMB];  // W_lm^T hi [N_PAD,512]
static __device__ __nv_bfloat16 g_Btl[(size_t)N_PAD * EMB];  // W_lm^T lo

// ============================================================================
// PTX helpers (arch-portable: sm_80-era instructions only)
// ============================================================================
__device__ __forceinline__ uint32_t smem_u32(const void* p) {
    uint32_t a;
    asm("{ .reg .u64 t; cvta.to.shared.u64 t, %1; cvt.u32.u64 %0, t; }"
        : "=r"(a) : "l"(p));
    return a;
}
__device__ __forceinline__ void cp_async16(uint32_t dst, const void* src) {
    asm volatile("cp.async.cg.shared.global [%0], [%1], 16;"
                 :: "r"(dst), "l"(src) : "memory");
}
__device__ __forceinline__ void cp_commit() {
    asm volatile("cp.async.commit_group;" ::: "memory");
}
template <int N>
__device__ __forceinline__ void cp_wait() {
    asm volatile("cp.async.wait_group %0;" :: "n"(N) : "memory");
}
__device__ __forceinline__ void ldm_x4(uint32_t* r, uint32_t addr) {
    asm volatile("ldmatrix.sync.aligned.m8n8.x4.shared.b16 {%0,%1,%2,%3}, [%4];"
                 : "=r"(r[0]), "=r"(r[1]), "=r"(r[2]), "=r"(r[3]) : "r"(addr));
}
__device__ __forceinline__ void mma16816(float* c, const uint32_t* a,
                                         uint32_t b0, uint32_t b1) {
    asm volatile(
        "mma.sync.aligned.m16n8k16.row.col.f32.bf16.bf16.f32 "
        "{%0,%1,%2,%3}, {%4,%5,%6,%7}, {%8,%9}, {%0,%1,%2,%3};"
        : "+f"(c[0]), "+f"(c[1]), "+f"(c[2]), "+f"(c[3])
        : "r"(a[0]), "r"(a[1]), "r"(a[2]), "r"(a[3]), "r"(b0), "r"(b1));
}

// ============================================================================
// Embedding
// ============================================================================
__global__ void embed_kernel(const int* __restrict__ idx,
                             const float* __restrict__ tok,
                             const float* __restrict__ pos,
                             float* __restrict__ x) {
    int n = blockIdx.x;
    int t = n & (TLEN - 1);
    int e4 = threadIdx.x;
    int token = __ldg(&idx[n]);
    float4 a = *(const float4*)&tok[(size_t)token * EMB + e4 * 4];
    float4 p = *(const float4*)&pos[(size_t)t * EMB + e4 * 4];
    a.x += p.x; a.y += p.y; a.z += p.z; a.w += p.w;
    *(float4*)&x[(size_t)n * EMB + e4 * 4] = a;
}

// ============================================================================
// SIMT GEMM (attention path). C = alpha * A * op(B)
// ============================================================================
template <bool NTMODE>
__global__ __launch_bounds__(256)
void gemm_kernel(const float* __restrict__ A, const float* __restrict__ B,
                 float* __restrict__ C,
                 int M, int N, int K, int lda, int ldb, int ldc,
                 long long sA, long long sB, long long sC, float alpha) {
    constexpr int BKS = 8, TM = 8, TN = 8;
    __shared__ float As[BKS][128];
    __shared__ float Bs[BKS][128];

    A += (long long)blockIdx.z * sA;
    B += (long long)blockIdx.z * sB;
    C += (long long)blockIdx.z * sC;

    const int tid = threadIdx.x;
    const int tx = tid % 16;
    const int ty = tid / 16;
    const int m0 = blockIdx.y * 128;
    const int n0 = blockIdx.x * 128;

    float acc[TM][TN];
#pragma unroll
    for (int i = 0; i < TM; ++i)
#pragma unroll
        for (int j = 0; j < TN; ++j) acc[i][j] = 0.f;

    const int arow = tid >> 1;
    const int acol = (tid & 1) * 4;

    for (int k0 = 0; k0 < K; k0 += BKS) {
        {
            float4 av = *(const float4*)&A[(size_t)(m0 + arow) * lda + (k0 + acol)];
            As[acol + 0][arow] = av.x;
            As[acol + 1][arow] = av.y;
            As[acol + 2][arow] = av.z;
            As[acol + 3][arow] = av.w;
        }
        if (!NTMODE) {
            int brow = tid >> 5;
            int bcol = (tid & 31) * 4;
            float4 bv = *(const float4*)&B[(size_t)(k0 + brow) * ldb + (n0 + bcol)];
            *(float4*)&Bs[brow][bcol] = bv;
        } else {
            int brow = tid >> 1;
            int bcol = (tid & 1) * 4;
            float4 bv = *(const float4*)&B[(size_t)(n0 + brow) * ldb + (k0 + bcol)];
            Bs[bcol + 0][brow] = bv.x;
            Bs[bcol + 1][brow] = bv.y;
            Bs[bcol + 2][brow] = bv.z;
            Bs[bcol + 3][brow] = bv.w;
        }
        __syncthreads();

#pragma unroll
        for (int k = 0; k < BKS; ++k) {
            float af[TM], bf[TN];
#pragma unroll
            for (int i = 0; i < TM; ++i) af[i] = As[k][ty * TM + i];
#pragma unroll
            for (int j = 0; j < TN; ++j) bf[j] = Bs[k][tx * TN + j];
#pragma unroll
            for (int i = 0; i < TM; ++i)
#pragma unroll
                for (int j = 0; j < TN; ++j)
                    acc[i][j] = fmaf(af[i], bf[j], acc[i][j]);
        }
        __syncthreads();
    }

#pragma unroll
    for (int i = 0; i < TM; ++i) {
        int m = m0 + ty * TM + i;
        float* crow = C + (size_t)m * ldc;
#pragma unroll
        for (int j0 = 0; j0 < TN; j0 += 4) {
            int n = n0 + tx * TN + j0;
            float4 r;
            r.x = alpha * acc[i][j0 + 0];
            r.y = alpha * acc[i][j0 + 1];
            r.z = alpha * acc[i][j0 + 2];
            r.w = alpha * acc[i][j0 + 3];
            *(float4*)&crow[n] = r;
        }
    }
}

// qkv fused: blockIdx.z selects W / output (same tiling as gemm_kernel NN)
__global__ __launch_bounds__(256)
void qkv_kernel(const float* __restrict__ X,
                const float* __restrict__ W0, const float* __restrict__ W1,
                const float* __restrict__ W2,
                float* __restrict__ C0, float* __restrict__ C1,
                float* __restrict__ C2) {
    constexpr int BKS = 8, TM = 8, TN = 8;
    __shared__ float As[BKS][128];
    __shared__ float Bs[BKS][128];

    const float* B = (blockIdx.z == 0) ? W0 : (blockIdx.z == 1) ? W1 : W2;
    float* C = (blockIdx.z == 0) ? C0 : (blockIdx.z == 1) ? C1 : C2;

    const int tid = threadIdx.x;
    const int tx = tid % 16;
    const int ty = tid / 16;
    const int m0 = blockIdx.y * 128;
    const int n0 = blockIdx.x * 128;

    float acc[TM][TN];
#pragma unroll
    for (int i = 0; i < TM; ++i)
#pragma unroll
        for (int j = 0; j < TN; ++j) acc[i][j] = 0.f;

    const int arow = tid >> 1;
    const int acol = (tid & 1) * 4;

    for (int k0 = 0; k0 < EMB; k0 += BKS) {
        {
            float4 av = *(const float4*)&X[(size_t)(m0 + arow) * EMB + (k0 + acol)];
            As[acol + 0][arow] = av.x;
            As[acol + 1][arow] = av.y;
            As[acol + 2][arow] = av.z;
            As[acol + 3][arow] = av.w;
        }
        {
            int brow = tid >> 5;
            int bcol = (tid & 31) * 4;
            float4 bv = *(const float4*)&B[(size_t)(k0 + brow) * EMB + (n0 + bcol)];
            *(float4*)&Bs[brow][bcol] = bv;
        }
        __syncthreads();

#pragma unroll
        for (int k = 0; k < BKS; ++k) {
            float af[TM], bf[TN];
#pragma unroll
            for (int i = 0; i < TM; ++i) af[i] = As[k][ty * TM + i];
#pragma unroll
            for (int j = 0; j < TN; ++j) bf[j] = Bs[k][tx * TN + j];
#pragma unroll
            for (int i = 0; i < TM; ++i)
#pragma unroll
                for (int j = 0; j < TN; ++j)
                    acc[i][j] = fmaf(af[i], bf[j], acc[i][j]);
        }
        __syncthreads();
    }

#pragma unroll
    for (int i = 0; i < TM; ++i) {
        int m = m0 + ty * TM + i;
        float* crow = C + (size_t)m * EMB;
#pragma unroll
        for (int j0 = 0; j0 < TN; j0 += 4) {
            int n = n0 + tx * TN + j0;
            float4 r;
            r.x = acc[i][j0 + 0];
            r.y = acc[i][j0 + 1];
            r.z = acc[i][j0 + 2];
            r.w = acc[i][j0 + 3];
            *(float4*)&crow[n] = r;
        }
    }
}

// ============================================================================
// Softmax over the QUERY axis (reference axis=1), causal-masked
// ============================================================================
__global__ void colstats_kernel(const float* __restrict__ wei,
                                float* __restrict__ cmax,
                                float* __restrict__ csum) {
    int b = blockIdx.y;
    int s = blockIdx.x * 32 + threadIdx.x;
    int ty = threadIdx.y;
    const float* w = wei + (size_t)b * TLEN * TLEN;
    float m = -INFINITY, l = 0.f;
    for (int t = ty; t < TLEN; t += 8) {
        if (t >= s) {
            float x = w[(size_t)t * TLEN + s];
            float nm = fmaxf(m, x);
            l = l * __expf(m - nm) + __expf(x - nm);
            m = nm;
        }
    }
    __shared__ float sm[8][33];
    __shared__ float sl[8][33];
    sm[ty][threadIdx.x] = m;
    sl[ty][threadIdx.x] = l;
    __syncthreads();
    if (ty == 0) {
        for (int j = 1; j < 8; ++j) {
            float m2 = sm[j][threadIdx.x], l2 = sl[j][threadIdx.x];
            if (l2 > 0.f) {
                float nm = fmaxf(m, m2);
                l = l * __expf(m - nm) + l2 * __expf(m2 - nm);
                m = nm;
            }
        }
        cmax[b * TLEN + s] = m;
        csum[b * TLEN + s] = l;
    }
}

__global__ void att_kernel(float* __restrict__ wei,
                           const float* __restrict__ cmax,
                           const float* __restrict__ csum) {
    int i = blockIdx.x * blockDim.x + threadIdx.x;
    int b = i >> 20;
    int r = i & (TLEN * TLEN - 1);
    int t = r >> 10;
    int s = r & (TLEN - 1);
    float v = 0.f;
    if (t >= s)
        v = __expf(wei[i] - cmax[b * TLEN + s]) / csum[b * TLEN + s];
    wei[i] = v;
}

// ============================================================================
// Split fp32 -> (bf16 hi, bf16 lo)
// ============================================================================
__global__ void split_a_kernel(const float* __restrict__ src,
                               __nv_bfloat16* __restrict__ hi,
                               __nv_bfloat16* __restrict__ lo) {
    int i = blockIdx.x * blockDim.x + threadIdx.x;
    float x = src[i];
    __nv_bfloat16 h = __float2bfloat16(x);
    hi[i] = h;
    lo[i] = __float2bfloat16(x - __bfloat162float(h));
}

// W_lm [512, VOC] -> Bt_hi/Bt_lo [N_PAD, 512], rows >= VOC zeroed
__global__ void transpose_split_kernel(const float* __restrict__ W,
                                       __nv_bfloat16* __restrict__ bh,
                                       __nv_bfloat16* __restrict__ bl) {
    __shared__ float t[32][33];
    int n0 = blockIdx.x * 32;
    int k0 = blockIdx.y * 32;
    for (int r = threadIdx.y; r < 32; r += 8) {
        int n = n0 + threadIdx.x;
        t[r][threadIdx.x] = (n < VOC) ? W[(size_t)(k0 + r) * VOC + n] : 0.f;
    }
    __syncthreads();
    for (int r = threadIdx.y; r < 32; r += 8) {
        float x = t[threadIdx.x][r];             // W[k0+tx][n0+r]
        __nv_bfloat16 h = __float2bfloat16(x);
        __nv_bfloat16 l = __float2bfloat16(x - __bfloat162float(h));
        size_t o = (size_t)(n0 + r) * EMB + k0 + threadIdx.x;
        bh[o] = h;
        bl[o] = l;
    }
}

// ============================================================================
// lm_head MMA GEMM: out[m,n] = sum_k (Ah+Al)[m,k]*(Bh+Bl)[n,k] + bias[n]
// (drops Al*Bl term, ~2^-16 relative). CTA 128x128, 8 warps (2m x 4n),
// BK=32 chunks, 2-stage cp.async double buffer, ldmatrix + mma.sync bf16.
// ============================================================================
__global__ __launch_bounds__(256, 1)
void lmhead_mma_kernel(const __nv_bfloat16* __restrict__ Ah,
                       const __nv_bfloat16* __restrict__ Al,
                       const __nv_bfloat16* __restrict__ Bh,
                       const __nv_bfloat16* __restrict__ Bl,
                       const float* __restrict__ bias,
                       float* __restrict__ out) {
    extern __shared__ char smem[];
    const uint32_t sbase = smem_u32(smem);
    const int tid = threadIdx.x;
    const int wid = tid >> 5;
    const int lane = tid & 31;
    const int m0 = blockIdx.x * BM;
    const int n0 = blockIdx.y * BN;
    const int wm = (wid >> 2) * 64;   // warp m offset (0 or 64)
    const int wn = (wid & 3) * 32;    // warp n offset (0,32,64,96)

    const __nv_bfloat16* srcs[4] = {
        Ah + (size_t)m0 * EMB, Al + (size_t)m0 * EMB,
        Bh + (size_t)n0 * EMB, Bl + (size_t)n0 * EMB };

    float acc[4][4][4];
#pragma unroll
    for (int i = 0; i < 4; ++i)
#pragma unroll
        for (int j = 0; j < 4; ++j)
#pragma unroll
            for (int q = 0; q < 4; ++q) acc[i][j][q] = 0.f;

    // cp.async issue of one k-chunk into a stage buffer
    auto issue = [&](int chunk, int stage) {
#pragma unroll
        for (int j = 0; j < 8; ++j) {
            int idx = tid + j * 256;            // [0, 2048)
            int t = idx >> 9;                   // tile 0..3
            int r = (idx >> 2) & 127;           // row 0..127
            int c = idx & 3;                    // 16B chunk 0..3
            const void* g = srcs[t] + (size_t)r * EMB + chunk * BKC + c * 8;
            uint32_t d = sbase + stage * STAGE_SM + t * TILE_SM + r * ROWB + c * 16;
            cp_async16(d, g);
        }
        cp_commit();
    };

    issue(0, 0);
    issue(1, 1);

    // per-thread ldmatrix row/col offsets (lanes 0-15: rows, k lo; 16-31: k hi)
    const int lrow = lane & 15;
    const int lcolhalf = (lane >> 4) * 16;

    for (int c = 0; c < NCHUNK; ++c) {
        if (c < NCHUNK - 2) cp_wait<1>(); else cp_wait<0>();
        __syncthreads();

        uint32_t stg = sbase + (c & 1) * STAGE_SM;
#pragma unroll
        for (int ks = 0; ks < 2; ++ks) {
            uint32_t kb = ks * 32 + lcolhalf;
            uint32_t aH[4][4], aL[4][4], bH[2][4], bL[2][4];
#pragma unroll
            for (int mi = 0; mi < 4; ++mi) {
                uint32_t ro = (wm + mi * 16 + lrow) * ROWB + kb;
                ldm_x4(aH[mi], stg + 0 * TILE_SM + ro);
                ldm_x4(aL[mi], stg + 1 * TILE_SM + ro);
            }
#pragma unroll
            for (int g = 0; g < 2; ++g) {
                uint32_t ro = (wn + g * 16 + lrow) * ROWB + kb;
                ldm_x4(bH[g], stg + 2 * TILE_SM + ro);
                ldm_x4(bL[g], stg + 3 * TILE_SM + ro);
            }
#pragma unroll
            for (int mi = 0; mi < 4; ++mi)
#pragma unroll
                for (int nj = 0; nj < 4; ++nj) {
                    int g = nj >> 1, p = nj & 1;
                    mma16816(acc[mi][nj], aH[mi], bH[g][p], bH[g][p + 2]);
                    mma16816(acc[mi][nj], aH[mi], bL[g][p], bL[g][p + 2]);
                    mma16816(acc[mi][nj], aL[mi], bH[g][p], bH[g][p + 2]);
                }
        }
        __syncthreads();
        if (c + 2 < NCHUNK) issue(c + 2, c & 1);
    }

    // epilogue: c-frag rows lane/4 (+8), cols (lane%4)*2 (+1)
#pragma unroll
    for (int mi = 0; mi < 4; ++mi) {
#pragma unroll
        for (int nj = 0; nj < 4; ++nj) {
            int mrow = m0 + wm + mi * 16 + (lane >> 2);
            int ncol = n0 + wn + nj * 8 + (lane & 3) * 2;
            float* p0 = out + (size_t)mrow * VOC + ncol;
            float* p1 = out + (size_t)(mrow + 8) * VOC + ncol;
            if (ncol < VOC) {
                float b0 = __ldg(&bias[ncol]);
                p0[0] = acc[mi][nj][0] + b0;
                p1[0] = acc[mi][nj][2] + b0;
            }
            if (ncol + 1 < VOC) {
                float b1 = __ldg(&bias[ncol + 1]);
                p0[1] = acc[mi][nj][1] + b1;
                p1[1] = acc[mi][nj][3] + b1;
            }
        }
    }
}

// ============================================================================
// Per-row NLL + mean
// ============================================================================
__global__ void rowloss_kernel(const float* __restrict__ logits,
                               const int* __restrict__ target,
                               float* __restrict__ rowloss) {
    int row = blockIdx.x;
    const float* p = logits + (size_t)row * VOC;
    float m = -INFINITY, l = 0.f;
    for (int j = threadIdx.x; j < VOC; j += blockDim.x) {
        float x = p[j];
        float nm = fmaxf(m, x);
        l = l * __expf(m - nm) + __expf(x - nm);
        m = nm;
    }
#pragma unroll
    for (int off = 16; off; off >>= 1) {
        float m2 = __shfl_xor_sync(0xFFFFFFFFu, m, off);
        float l2 = __shfl_xor_sync(0xFFFFFFFFu, l, off);
        float nm = fmaxf(m, m2);
        l = l * __expf(m - nm) + l2 * __expf(m2 - nm);
        m = nm;
    }
    __shared__ float sm[8], sl[8];
    int w = threadIdx.x >> 5;
    if ((threadIdx.x & 31) == 0) { sm[w] = m; sl[w] = l; }
    __syncthreads();
    if (threadIdx.x == 0) {
        m = sm[0]; l = sl[0];
        for (int j = 1; j < 8; ++j) {
            float m2 = sm[j], l2 = sl[j];
            float nm = fmaxf(m, m2);
            l = l * __expf(m - nm) + l2 * __expf(m2 - nm);
            m = nm;
        }
        float lse = m + logf(l);
        rowloss[row] = lse - p[target[row]];
    }
}

__global__ void loss_reduce_kernel(const float* __restrict__ rowloss,
                                   float* __restrict__ out) {
    __shared__ float s[256];
    float acc = 0.f;
    for (int j = threadIdx.x; j < MALL; j += 256) acc += rowloss[j];
    s[threadIdx.x] = acc;
    __syncthreads();
    for (int o = 128; o; o >>= 1) {
        if (threadIdx.x < o) s[threadIdx.x] += s[threadIdx.x + o];
        __syncthreads();
    }
    if (threadIdx.x == 0) *out = s[0] / (float)MALL;
}

// ============================================================================
extern "C" void kernel_launch(void* const* d_in, const int* in_sizes, int n_in,
                              void* d_out, int out_size) {
    const int*   idx    = (const int*)d_in[0];
    const int*   target = (const int*)d_in[1];
    const float* tok    = (const float*)d_in[2];
    const float* pos    = (const float*)d_in[3];
    const float* Wk     = (const float*)d_in[4];
    const float* Wq     = (const float*)d_in[5];
    const float* Wv     = (const float*)d_in[6];
    const float* Wlm    = (const float*)d_in[7];
    const float* blm    = (const float*)d_in[8];
    float* out = (float*)d_out;

    float *X, *Kb, *Qb, *Vb, *WEI, *O, *cmax, *csum, *rl;
    __nv_bfloat16 *Ah, *Al, *Bth, *Btl;
    cudaGetSymbolAddress((void**)&X,    g_X);
    cudaGetSymbolAddress((void**)&Kb,   g_K);
    cudaGetSymbolAddress((void**)&Qb,   g_Q);
    cudaGetSymbolAddress((void**)&Vb,   g_V);
    cudaGetSymbolAddress((void**)&WEI,  g_WEI);
    cudaGetSymbolAddress((void**)&O,    g_O);
    cudaGetSymbolAddress((void**)&cmax, g_cmax);
    cudaGetSymbolAddress((void**)&csum, g_csum);
    cudaGetSymbolAddress((void**)&rl,   g_rowloss);
    cudaGetSymbolAddress((void**)&Ah,   g_Ah);
    cudaGetSymbolAddress((void**)&Al,   g_Al);
    cudaGetSymbolAddress((void**)&Bth,  g_Bth);
    cudaGetSymbolAddress((void**)&Btl,  g_Btl);

    cudaFuncSetAttribute(lmhead_mma_kernel,
                         cudaFuncAttributeMaxDynamicSharedMemorySize, SMEM_TOTAL_TC);

    const float scale = 0.044194173824159216f;  // 512^-0.5 (n_embed, not head)

    // 0) W_lm transpose + bf16 split (independent)
    transpose_split_kernel<<<dim3(N_PAD / 32, EMB / 32), dim3(32, 8)>>>(Wlm, Bth, Btl);

    // 1) x = tok_emb[idx] + pos_emb
    embed_kernel<<<MALL, 128>>>(idx, tok, pos, X);

    // 2) k,q,v = x @ W (one z-batched launch)
    qkv_kernel<<<dim3(EMB / 128, MALL / 128, 3), 256>>>(X, Wk, Wq, Wv, Kb, Qb, Vb);

    // 3) wei = scale * q @ k^T
    {
        dim3 g(TLEN / 128, TLEN / 128, BATCH);
        gemm_kernel<true><<<g, 256>>>(Qb, Kb, WEI, TLEN, TLEN, EMB, EMB, EMB, TLEN,
                                      (long long)TLEN * EMB, (long long)TLEN * EMB,
                                      (long long)TLEN * TLEN, scale);
    }

    // 4) softmax over the query axis
    colstats_kernel<<<dim3(TLEN / 32, BATCH), dim3(32, 8)>>>(WEI, cmax, csum);
    att_kernel<<<(BATCH * TLEN * TLEN) / 256, 256>>>(WEI, cmax, csum);

    // 5) out = att @ v
    {
        dim3 g(EMB / 128, TLEN / 128, BATCH);
        gemm_kernel<false><<<g, 256>>>(WEI, Vb, O, TLEN, EMB, TLEN, TLEN, EMB, EMB,
                                       (long long)TLEN * TLEN, (long long)TLEN * EMB,
                                       (long long)TLEN * EMB, 1.f);
    }

    // 6) bf16 split of O, then tensor-core lm_head GEMM -> d_out
    split_a_kernel<<<(MALL * EMB) / 256, 256>>>(O, Ah, Al);
    lmhead_mma_kernel<<<dim3(NTILES_M, NTILES_N), 256, SMEM_TOTAL_TC>>>(
        Ah, Al, Bth, Btl, blm, out);

    // 7) loss
    rowloss_kernel<<<MALL, 256>>>(out, target, rl);
    loss_reduce_kernel<<<1, 256>>>(rl, out + (size_t)out_size - 1);
}